// round 1
// baseline (speedup 1.0000x reference)
#include <cuda_runtime.h>

#define TN   8192
#define DD   512
#define NPER 4
#define KNN  5     // K-1 neighbors kept (K=6)
#define BM   32
#define BN   128
#define BK   32

__device__ float g_sqn[TN];
__device__ int   g_nn[TN * KNN];
__device__ int   g_choice_is32;

// ---------------------------------------------------------------------------
// Kernel 0: row squared norms (one block of 128 threads per row).
// Also resets the dtype-detection flag (runs first in the stream).
// ---------------------------------------------------------------------------
__global__ void sqnorm_kernel(const float* __restrict__ A) {
    if (blockIdx.x == 0 && threadIdx.x == 0) g_choice_is32 = 0;
    int row = blockIdx.x;
    const float4* p = reinterpret_cast<const float4*>(A + (size_t)row * DD);
    float4 v = p[threadIdx.x];
    float s = v.x * v.x + v.y * v.y + v.z * v.z + v.w * v.w;
#pragma unroll
    for (int off = 16; off > 0; off >>= 1)
        s += __shfl_xor_sync(0xffffffffu, s, off);
    __shared__ float ws[4];
    int lane = threadIdx.x & 31, wid = threadIdx.x >> 5;
    if (lane == 0) ws[wid] = s;
    __syncthreads();
    if (threadIdx.x == 0) g_sqn[row] = ws[0] + ws[1] + ws[2] + ws[3];
}

// ---------------------------------------------------------------------------
// Kernel 1: detect whether nn_choice is int64 or int32 on this harness.
// Values are in [0,5). If int64 (little-endian), every odd 32-bit word is 0.
// If int32, 16384 random values in [0,5) have a nonzero odd word w.p. ~1.
// Only reads the first 32768 words, which is safe under either layout.
// ---------------------------------------------------------------------------
__global__ void detect_kernel(const unsigned int* __restrict__ w) {
    int idx = blockIdx.x * blockDim.x + threadIdx.x;   // 0..16383
    if (w[2 * idx + 1] != 0u) atomicOr(&g_choice_is32, 1);
}

// ---------------------------------------------------------------------------
// Kernel 2: fused distance GEMM + per-row top-5 selection.
// Grid: TN/BM = 256 blocks, 256 threads. Each block owns 32 rows, sweeps all
// 8192 columns in 128-wide tiles; each thread computes a 4x4 outer-product
// block and maintains sorted top-5 (value, index) lists for its 4 rows.
// Distances compared as  val = sq[j] - 2*dot(i,j)   (order-equivalent to d2).
// ---------------------------------------------------------------------------
__device__ __forceinline__ bool kless(float v, int id, float w, int jd) {
    return (v < w) || (v == w && id < jd);
}

__global__ __launch_bounds__(256, 2)
void knn_kernel(const float* __restrict__ A) {
    // tiles: As [BK][36] (k-major, padded), Bs [BK][132]; reused for the merge
    __shared__ __align__(16) float sm[BK * 36 + BK * 132];  // 21504 B
    float* As = sm;
    float* Bs = sm + BK * 36;

    const int tid  = threadIdx.x;
    const int tx   = tid & 31;   // column group: cols tx*4 .. tx*4+3
    const int ty   = tid >> 5;   // row group:    rows ty*4 .. ty*4+3
    const int brow = blockIdx.x * BM;

    float tv[4][KNN];
    int   ti[4][KNN];
#pragma unroll
    for (int r = 0; r < 4; ++r)
#pragma unroll
        for (int s = 0; s < KNN; ++s) { tv[r][s] = 3.4e38f; ti[r][s] = 0x7fffffff; }

    const int ld_row_a = tid >> 3;          // 0..31
    const int ld_ka    = (tid & 7) << 2;    // 0,4,..,28

    for (int jt = 0; jt < TN; jt += BN) {
        float acc[4][4];
#pragma unroll
        for (int r = 0; r < 4; ++r)
#pragma unroll
            for (int c = 0; c < 4; ++c) acc[r][c] = 0.0f;

        for (int kt = 0; kt < DD; kt += BK) {
            // load A_i tile (32 x 32), transposed into As[k][row]
            {
                float4 va = *reinterpret_cast<const float4*>(
                    A + (size_t)(brow + ld_row_a) * DD + kt + ld_ka);
                As[(ld_ka + 0) * 36 + ld_row_a] = va.x;
                As[(ld_ka + 1) * 36 + ld_row_a] = va.y;
                As[(ld_ka + 2) * 36 + ld_row_a] = va.z;
                As[(ld_ka + 3) * 36 + ld_row_a] = va.w;
            }
            // load A_j tile (128 x 32), transposed into Bs[k][col]
#pragma unroll
            for (int it = 0; it < 4; ++it) {
                int f   = tid + it * 256;
                int row = f >> 3;
                int kq  = (f & 7) << 2;
                float4 vb = *reinterpret_cast<const float4*>(
                    A + (size_t)(jt + row) * DD + kt + kq);
                Bs[(kq + 0) * 132 + row] = vb.x;
                Bs[(kq + 1) * 132 + row] = vb.y;
                Bs[(kq + 2) * 132 + row] = vb.z;
                Bs[(kq + 3) * 132 + row] = vb.w;
            }
            __syncthreads();
#pragma unroll
            for (int k = 0; k < BK; ++k) {
                float4 a = *reinterpret_cast<const float4*>(As + k * 36  + ty * 4);
                float4 b = *reinterpret_cast<const float4*>(Bs + k * 132 + tx * 4);
                acc[0][0] += a.x * b.x; acc[0][1] += a.x * b.y;
                acc[0][2] += a.x * b.z; acc[0][3] += a.x * b.w;
                acc[1][0] += a.y * b.x; acc[1][1] += a.y * b.y;
                acc[1][2] += a.y * b.z; acc[1][3] += a.y * b.w;
                acc[2][0] += a.z * b.x; acc[2][1] += a.z * b.y;
                acc[2][2] += a.z * b.z; acc[2][3] += a.z * b.w;
                acc[3][0] += a.w * b.x; acc[3][1] += a.w * b.y;
                acc[3][2] += a.w * b.z; acc[3][3] += a.w * b.w;
            }
            __syncthreads();
        }

        // epilogue: update top-5 lists
        float4 sq4 = *reinterpret_cast<const float4*>(g_sqn + jt + tx * 4);
        float sqc[4] = {sq4.x, sq4.y, sq4.z, sq4.w};
#pragma unroll
        for (int r = 0; r < 4; ++r) {
            int irow = brow + ty * 4 + r;
#pragma unroll
            for (int c = 0; c < 4; ++c) {
                int j = jt + tx * 4 + c;
                float val = sqc[c] - 2.0f * acc[r][c];
                if (j != irow && kless(val, j, tv[r][KNN - 1], ti[r][KNN - 1])) {
                    tv[r][KNN - 1] = val; ti[r][KNN - 1] = j;
#pragma unroll
                    for (int p = KNN - 1; p > 0; --p) {
                        if (kless(tv[r][p], ti[r][p], tv[r][p - 1], ti[r][p - 1])) {
                            float fv = tv[r][p]; tv[r][p] = tv[r][p - 1]; tv[r][p - 1] = fv;
                            int   iv = ti[r][p]; ti[r][p] = ti[r][p - 1]; ti[r][p - 1] = iv;
                        }
                    }
                }
            }
        }
    }

    // -------- merge: 32 per-thread lists per row -> final sorted top-5 -------
    // reuse tile smem; two half-passes of 16 rows each (16*32*5 entries)
    float* cv = sm;
    int*   ci = reinterpret_cast<int*>(sm + 16 * 32 * KNN);
#pragma unroll
    for (int h = 0; h < 2; ++h) {
        __syncthreads();
#pragma unroll
        for (int r = 0; r < 4; ++r) {
            int R = ty * 4 + r;
            if ((R >> 4) == h) {
                int base = ((R & 15) * 32 + tx) * KNN;
#pragma unroll
                for (int s = 0; s < KNN; ++s) { cv[base + s] = tv[r][s]; ci[base + s] = ti[r][s]; }
            }
        }
        __syncthreads();
        if (tid < 16) {
            float bv[KNN]; int bi[KNN];
#pragma unroll
            for (int s = 0; s < KNN; ++s) { bv[s] = 3.4e38f; bi[s] = 0x7fffffff; }
            int base = tid * (32 * KNN);
            for (int e = 0; e < 32 * KNN; ++e) {
                float v = cv[base + e]; int id = ci[base + e];
                if (kless(v, id, bv[KNN - 1], bi[KNN - 1])) {
                    bv[KNN - 1] = v; bi[KNN - 1] = id;
#pragma unroll
                    for (int p = KNN - 1; p > 0; --p) {
                        if (kless(bv[p], bi[p], bv[p - 1], bi[p - 1])) {
                            float fv = bv[p]; bv[p] = bv[p - 1]; bv[p - 1] = fv;
                            int   iv = bi[p]; bi[p] = bi[p - 1]; bi[p - 1] = iv;
                        }
                    }
                }
            }
            int grow = brow + h * 16 + tid;
#pragma unroll
            for (int s = 0; s < KNN; ++s) g_nn[grow * KNN + s] = bi[s];
        }
    }
}

// ---------------------------------------------------------------------------
// Kernel 3: SMOTE interpolation. One block (128 threads) per output row.
// out[i*NPER+n] = a[i] + gap * (a[nn_idx[i][choice]] - a[i])
// ---------------------------------------------------------------------------
__global__ void populate_kernel(const float* __restrict__ A,
                                const float* __restrict__ gaps,
                                const unsigned int* __restrict__ cw,
                                float* __restrict__ out) {
    int o = blockIdx.x;
    int i = o >> 2;                     // NPER = 4
    float g = gaps[o];
    int widx = g_choice_is32 ? o : (o << 1);   // int32 vs int64 low word
    int c  = (int)cw[widx];
    int nb = g_nn[i * KNN + c];
    const float4* ai = reinterpret_cast<const float4*>(A + (size_t)i  * DD);
    const float4* an = reinterpret_cast<const float4*>(A + (size_t)nb * DD);
    float4* op = reinterpret_cast<float4*>(out) + (size_t)o * (DD / 4);
    int t = threadIdx.x;                // 128 threads * float4 = 512 floats
    float4 a = ai[t], b = an[t];
    float4 r;
    r.x = a.x + g * (b.x - a.x);
    r.y = a.y + g * (b.y - a.y);
    r.z = a.z + g * (b.z - a.z);
    r.w = a.w + g * (b.w - a.w);
    op[t] = r;
}

// ---------------------------------------------------------------------------
extern "C" void kernel_launch(void* const* d_in, const int* in_sizes, int n_in,
                              void* d_out, int out_size) {
    const float* A            = (const float*)d_in[0];        // [8192,512] f32
    const float* gaps         = (const float*)d_in[1];        // [8192,4]   f32
    const unsigned int* cw    = (const unsigned int*)d_in[2]; // nn_choice (i32 or i64)
    float* out                = (float*)d_out;                // [32768,512] f32

    sqnorm_kernel<<<TN, 128>>>(A);
    detect_kernel<<<64, 256>>>(cw);
    knn_kernel<<<TN / BM, 256>>>(A);
    populate_kernel<<<TN * NPER, 128>>>(A, gaps, cw, out);
}

// round 3
// speedup vs baseline: 2.1018x; 2.1018x over previous
#include <cuda_runtime.h>
#include <cuda_bf16.h>
#include <cstdint>

#define TN    8192
#define DD    512
#define NPER  4
#define KNN   5
#define NCAND 8

#define KM        128                    // rows per CTA
#define KNT       128                    // j cols per tile
#define JHALF     (TN / 2)
#define NTILES    (JHALF / KNT)          // 32
#define KCH       32                     // bf16 k elems per chunk
#define NCH       (DD / KCH)             // 16
#define RSTRIDE_B 80                     // bytes per smem row (32 bf16 + 8 pad)
#define TILE_B    (KM * RSTRIDE_B)       // 10240 B per operand tile
#define OP_STAGE  (4 * TILE_B)           // AiH, AiL, AjH, AjL
#define OFF_D     (2 * OP_STAGE)         // 81920
#define DSTRIDE   130                    // f32 elems
#define OFF_SQS   (OFF_D + KM * DSTRIDE * 4)   // 148480
#define SMEM_TOTAL (OFF_SQS + 512)             // 148992

__device__ float          g_sqn[TN];
__device__ int            g_nn[TN * KNN];
__device__ int            g_choice_is32;
__device__ __nv_bfloat16  g_Ahi[TN * DD];
__device__ __nv_bfloat16  g_Alo[TN * DD];
__device__ int            g_cand_i[TN * 2 * NCAND];

// ============================ helpers =======================================
__device__ __forceinline__ uint32_t smem_u32(const void* p) {
    uint32_t a;
    asm("{ .reg .u64 t; cvta.to.shared.u64 t, %1; cvt.u32.u64 %0, t; }"
        : "=r"(a) : "l"(p));
    return a;
}
__device__ __forceinline__ void cp16(uint32_t dst, const void* src) {
    asm volatile("cp.async.cg.shared.global [%0], [%1], 16;"
                 :: "r"(dst), "l"(src) : "memory");
}
__device__ __forceinline__ void cp_commit() {
    asm volatile("cp.async.commit_group;" ::: "memory");
}
__device__ __forceinline__ void cp_wait0() {
    asm volatile("cp.async.wait_group 0;" ::: "memory");
}
__device__ __forceinline__ void cp_wait1() {
    asm volatile("cp.async.wait_group 1;" ::: "memory");
}
__device__ __forceinline__ void ldsm4(uint32_t* r, uint32_t a) {
    asm volatile("ldmatrix.sync.aligned.m8n8.x4.shared.b16 {%0,%1,%2,%3}, [%4];"
                 : "=r"(r[0]), "=r"(r[1]), "=r"(r[2]), "=r"(r[3]) : "r"(a));
}
__device__ __forceinline__ void mma16816(float* c, const uint32_t* a,
                                         uint32_t b0, uint32_t b1) {
    asm volatile("mma.sync.aligned.m16n8k16.row.col.f32.bf16.bf16.f32 "
                 "{%0,%1,%2,%3}, {%4,%5,%6,%7}, {%8,%9}, {%0,%1,%2,%3};"
                 : "+f"(c[0]), "+f"(c[1]), "+f"(c[2]), "+f"(c[3])
                 : "r"(a[0]), "r"(a[1]), "r"(a[2]), "r"(a[3]),
                   "r"(b0), "r"(b1));
}
__device__ __forceinline__ bool kless(float v, int id, float w, int jd) {
    return (v < w) || (v == w && id < jd);
}
template <int NC>
__device__ __forceinline__ void topk_insert(float (&kv)[NC], int (&ki)[NC],
                                            float v, int j) {
    if (kless(v, j, kv[NC - 1], ki[NC - 1])) {
        kv[NC - 1] = v; ki[NC - 1] = j;
#pragma unroll
        for (int p = NC - 1; p > 0; --p) {
            if (kless(kv[p], ki[p], kv[p - 1], ki[p - 1])) {
                float tv = kv[p]; kv[p] = kv[p - 1]; kv[p - 1] = tv;
                int   tj = ki[p]; ki[p] = ki[p - 1]; ki[p - 1] = tj;
            }
        }
    }
}

// ======================= fp32 -> bf16 hi/lo =================================
__global__ void convert_kernel(const float* __restrict__ A) {
    int idx = blockIdx.x * blockDim.x + threadIdx.x;
    float4 v = reinterpret_cast<const float4*>(A)[idx];
    __nv_bfloat16 h0 = __float2bfloat16(v.x), h1 = __float2bfloat16(v.y);
    __nv_bfloat16 h2 = __float2bfloat16(v.z), h3 = __float2bfloat16(v.w);
    __nv_bfloat16 l0 = __float2bfloat16(v.x - __bfloat162float(h0));
    __nv_bfloat16 l1 = __float2bfloat16(v.y - __bfloat162float(h1));
    __nv_bfloat16 l2 = __float2bfloat16(v.z - __bfloat162float(h2));
    __nv_bfloat16 l3 = __float2bfloat16(v.w - __bfloat162float(h3));
    __nv_bfloat162* ph = reinterpret_cast<__nv_bfloat162*>(g_Ahi);
    __nv_bfloat162* pl = reinterpret_cast<__nv_bfloat162*>(g_Alo);
    ph[idx * 2 + 0] = __nv_bfloat162(h0, h1);
    ph[idx * 2 + 1] = __nv_bfloat162(h2, h3);
    pl[idx * 2 + 0] = __nv_bfloat162(l0, l1);
    pl[idx * 2 + 1] = __nv_bfloat162(l2, l3);
}

// ============================ sq norms ======================================
__global__ void sqnorm_kernel(const float* __restrict__ A) {
    if (blockIdx.x == 0 && threadIdx.x == 0) g_choice_is32 = 0;
    int row = blockIdx.x;
    const float4* p = reinterpret_cast<const float4*>(A + (size_t)row * DD);
    float4 v = p[threadIdx.x];
    float s = v.x * v.x + v.y * v.y + v.z * v.z + v.w * v.w;
#pragma unroll
    for (int off = 16; off > 0; off >>= 1) s += __shfl_xor_sync(0xffffffffu, s, off);
    __shared__ float ws[4];
    int lane = threadIdx.x & 31, wid = threadIdx.x >> 5;
    if (lane == 0) ws[wid] = s;
    __syncthreads();
    if (threadIdx.x == 0) g_sqn[row] = ws[0] + ws[1] + ws[2] + ws[3];
}

// ===================== int32-vs-int64 detection =============================
__global__ void detect_kernel(const unsigned int* __restrict__ w) {
    int idx = blockIdx.x * blockDim.x + threadIdx.x;
    if (w[2 * idx + 1] != 0u) atomicOr(&g_choice_is32, 1);
}

// ================== tensor-core (mma.sync) kNN ==============================
// grid = 128 (64 row-blocks x 2 j-halves), 256 threads (8 warps, 2x4 warp grid)
__global__ __launch_bounds__(256, 1) void knn_mma_kernel() {
    extern __shared__ __align__(16) char smc[];
    const uint32_t sb = smem_u32(smc);
    const int tid  = threadIdx.x;
    const int lane = tid & 31;
    const int wid  = tid >> 5;
    const int wm   = wid >> 2;      // 0..1 -> rows wm*64
    const int wn   = wid & 3;       // 0..3 -> cols wn*32
    const int ib   = blockIdx.x >> 1;
    const int half = blockIdx.x & 1;
    const int brow = ib * KM;
    const int jbase = half * JHALF;

    float kv[NCAND]; int ki[NCAND];
#pragma unroll
    for (int s = 0; s < NCAND; ++s) { kv[s] = 3.4e38f; ki[s] = 0x7fffffff; }

    const int flat0 = tid * 2;
    const int lrow = lane & 15;
    const int lcol = lane >> 4;

    for (int t = 0; t < NTILES; ++t) {
        const int jb = jbase + t * KNT;

        float acc[4][4][4];
#pragma unroll
        for (int a = 0; a < 4; ++a)
#pragma unroll
            for (int b = 0; b < 4; ++b)
#pragma unroll
                for (int c = 0; c < 4; ++c) acc[a][b][c] = 0.0f;

        // ---- chunk pipeline: double-buffered cp.async ----
        // load chunk 0
        {
            const uint32_t stg = sb;
#pragma unroll
            for (int i = 0; i < 2; ++i) {
                int flat = flat0 + i;
                int r = flat >> 2, q = flat & 3;
                uint32_t dofs = (uint32_t)(r * RSTRIDE_B + q * 16);
                size_t gi = (size_t)(brow + r) * DD + q * 8;
                size_t gj = (size_t)(jb   + r) * DD + q * 8;
                cp16(stg + 0 * TILE_B + dofs, g_Ahi + gi);
                cp16(stg + 1 * TILE_B + dofs, g_Alo + gi);
                cp16(stg + 2 * TILE_B + dofs, g_Ahi + gj);
                cp16(stg + 3 * TILE_B + dofs, g_Alo + gj);
            }
            cp_commit();
        }

        for (int c = 0; c < NCH; ++c) {
            if (c + 1 < NCH) {
                const uint32_t stg = sb + ((c + 1) & 1) * OP_STAGE;
                const int kt = (c + 1) * KCH;
#pragma unroll
                for (int i = 0; i < 2; ++i) {
                    int flat = flat0 + i;
                    int r = flat >> 2, q = flat & 3;
                    uint32_t dofs = (uint32_t)(r * RSTRIDE_B + q * 16);
                    size_t gi = (size_t)(brow + r) * DD + kt + q * 8;
                    size_t gj = (size_t)(jb   + r) * DD + kt + q * 8;
                    cp16(stg + 0 * TILE_B + dofs, g_Ahi + gi);
                    cp16(stg + 1 * TILE_B + dofs, g_Alo + gi);
                    cp16(stg + 2 * TILE_B + dofs, g_Ahi + gj);
                    cp16(stg + 3 * TILE_B + dofs, g_Alo + gj);
                }
                cp_commit();
                cp_wait1();
            } else {
                cp_wait0();
            }
            __syncthreads();

            // ---- MMA on stage c&1 ----
            const uint32_t base = sb + (c & 1) * OP_STAGE;
#pragma unroll
            for (int ks = 0; ks < 2; ++ks) {
                uint32_t aH[4][4], aL[4][4], bH[2][4], bL[2][4];
                const uint32_t kof = (uint32_t)(ks * 32 + lcol * 16);
#pragma unroll
                for (int mt = 0; mt < 4; ++mt) {
                    uint32_t ad = base +
                        (uint32_t)((wm * 64 + mt * 16 + lrow) * RSTRIDE_B) + kof;
                    ldsm4(aH[mt], ad);
                    ldsm4(aL[mt], ad + TILE_B);
                }
#pragma unroll
                for (int np = 0; np < 2; ++np) {
                    uint32_t ad = base + 2 * TILE_B +
                        (uint32_t)((wn * 32 + np * 16 + lrow) * RSTRIDE_B) + kof;
                    ldsm4(bH[np], ad);
                    ldsm4(bL[np], ad + TILE_B);
                }
#pragma unroll
                for (int mt = 0; mt < 4; ++mt)
#pragma unroll
                    for (int nt = 0; nt < 4; ++nt) {
                        const int np = nt >> 1, sel = nt & 1;
                        mma16816(acc[mt][nt], aH[mt], bH[np][sel], bH[np][sel + 2]);
                        mma16816(acc[mt][nt], aH[mt], bL[np][sel], bL[np][sel + 2]);
                        mma16816(acc[mt][nt], aL[mt], bH[np][sel], bH[np][sel + 2]);
                    }
            }
            __syncthreads();
        }

        // ---- stage d2 dot values + sq[j] to smem ----
        if (tid < 128)
            *(float*)(smc + OFF_SQS + tid * 4) = g_sqn[jb + tid];
        {
            float* Dst = (float*)(smc + OFF_D);
            const int m0 = wm * 64 + (lane >> 2);
            const int n0 = wn * 32 + (lane & 3) * 2;
#pragma unroll
            for (int mt = 0; mt < 4; ++mt)
#pragma unroll
                for (int nt = 0; nt < 4; ++nt) {
                    float2 v01 = make_float2(acc[mt][nt][0], acc[mt][nt][1]);
                    float2 v23 = make_float2(acc[mt][nt][2], acc[mt][nt][3]);
                    *(float2*)(Dst + (m0 + mt * 16    ) * DSTRIDE + n0 + nt * 8) = v01;
                    *(float2*)(Dst + (m0 + mt * 16 + 8) * DSTRIDE + n0 + nt * 8) = v23;
                }
        }
        __syncthreads();

        // ---- selection: thread (row = tid&127, col-half = tid>>7) ----
        {
            const int row = tid & 127, ch = tid >> 7;
            const int grow = brow + row;
            const float* Dp  = (const float*)(smc + OFF_D) + row * DSTRIDE + ch * 64;
            const float* sqp = (const float*)(smc + OFF_SQS) + ch * 64;
            const int j0 = jb + ch * 64;
#pragma unroll 8
            for (int n = 0; n < 64; ++n) {
                int j = j0 + n;
                float val = sqp[n] - 2.0f * Dp[n];
                if (j != grow) topk_insert<NCAND>(kv, ki, val, j);
            }
        }
        // next-tile chunk-loop syncthreads separate selection reads from reuse
    }

    // ---- merge thread pairs (row, colhalf 0/1) and write candidates --------
    __syncthreads();
    {
        float* mv = (float*)(smc + OFF_D);
        int*   mi = (int*)(smc + OFF_D) + 256 * NCAND;
#pragma unroll
        for (int s = 0; s < NCAND; ++s) {
            mv[tid * NCAND + s] = kv[s];
            mi[tid * NCAND + s] = ki[s];
        }
    }
    __syncthreads();
    if (tid < 128) {
        const int o = tid + 128;
        float* mv = (float*)(smc + OFF_D);
        int*   mi = (int*)(smc + OFF_D) + 256 * NCAND;
#pragma unroll
        for (int s = 0; s < NCAND; ++s)
            topk_insert<NCAND>(kv, ki, mv[o * NCAND + s], mi[o * NCAND + s]);
        const int grow = brow + tid;
        const int base = (grow * 2 + half) * NCAND;
#pragma unroll
        for (int s = 0; s < NCAND; ++s) g_cand_i[base + s] = ki[s];
    }
}

// ========= exact fp32 rescore of 16 candidates -> top-5 =====================
__global__ void rescore_kernel(const float* __restrict__ A) {
    const int row = blockIdx.x;
    const int w = threadIdx.x >> 5, lane = threadIdx.x & 31;  // 16 warps
    __shared__ float sv[16];
    __shared__ int   si[16];
    const int j = g_cand_i[row * 16 + w];
    const float* ai = A + (size_t)row * DD;
    const float* aj = A + (size_t)j * DD;
    float dot = 0.0f;
#pragma unroll
    for (int k = 0; k < 16; ++k) dot += ai[lane + k * 32] * aj[lane + k * 32];
#pragma unroll
    for (int off = 16; off > 0; off >>= 1) dot += __shfl_xor_sync(0xffffffffu, dot, off);
    if (lane == 0) { sv[w] = g_sqn[j] - 2.0f * dot; si[w] = j; }
    __syncthreads();
    if (threadIdx.x == 0) {
        float bv[KNN]; int bi[KNN];
#pragma unroll
        for (int s = 0; s < KNN; ++s) { bv[s] = 3.4e38f; bi[s] = 0x7fffffff; }
        for (int e = 0; e < 16; ++e) {
            float v = sv[e]; int id = si[e];
            if (kless(v, id, bv[KNN - 1], bi[KNN - 1])) {
                bv[KNN - 1] = v; bi[KNN - 1] = id;
#pragma unroll
                for (int p = KNN - 1; p > 0; --p) {
                    if (kless(bv[p], bi[p], bv[p - 1], bi[p - 1])) {
                        float fv = bv[p]; bv[p] = bv[p - 1]; bv[p - 1] = fv;
                        int   iv = bi[p]; bi[p] = bi[p - 1]; bi[p - 1] = iv;
                    }
                }
            }
        }
#pragma unroll
        for (int s = 0; s < KNN; ++s) g_nn[row * KNN + s] = bi[s];
    }
}

// ===================== SMOTE interpolation ==================================
__global__ void populate_kernel(const float* __restrict__ A,
                                const float* __restrict__ gaps,
                                const unsigned int* __restrict__ cw,
                                float* __restrict__ out) {
    int o = blockIdx.x;
    int i = o >> 2;
    float g = gaps[o];
    int widx = g_choice_is32 ? o : (o << 1);
    int c  = (int)cw[widx];
    int nb = g_nn[i * KNN + c];
    const float4* ai = reinterpret_cast<const float4*>(A + (size_t)i  * DD);
    const float4* an = reinterpret_cast<const float4*>(A + (size_t)nb * DD);
    float4* op = reinterpret_cast<float4*>(out) + (size_t)o * (DD / 4);
    int t = threadIdx.x;
    float4 a = ai[t], b = an[t];
    float4 r;
    r.x = a.x + g * (b.x - a.x);
    r.y = a.y + g * (b.y - a.y);
    r.z = a.z + g * (b.z - a.z);
    r.w = a.w + g * (b.w - a.w);
    op[t] = r;
}

// ============================================================================
extern "C" void kernel_launch(void* const* d_in, const int* in_sizes, int n_in,
                              void* d_out, int out_size) {
    const float* A         = (const float*)d_in[0];
    const float* gaps      = (const float*)d_in[1];
    const unsigned int* cw = (const unsigned int*)d_in[2];
    float* out             = (float*)d_out;

    cudaFuncSetAttribute(knn_mma_kernel,
                         cudaFuncAttributeMaxDynamicSharedMemorySize, SMEM_TOTAL);

    convert_kernel<<<TN * DD / 4 / 256, 256>>>(A);
    sqnorm_kernel<<<TN, 128>>>(A);
    detect_kernel<<<64, 256>>>(cw);
    knn_mma_kernel<<<128, 256, SMEM_TOTAL>>>();
    rescore_kernel<<<TN, 512>>>(A);
    populate_kernel<<<TN * NPER, 128>>>(A, gaps, cw, out);
}

// round 4
// speedup vs baseline: 2.7896x; 1.3272x over previous
#include <cuda_runtime.h>
#include <cuda_bf16.h>
#include <cstdint>

#define TN    8192
#define DD    512
#define NPER  4
#define KNN   5
#define NCAND 8

#define KM      128
#define KNT     128
#define JHALF   (TN / 2)
#define NTILES  (JHALF / KNT)        // 32
#define KCH     64                   // bf16 k per chunk (128B rows, SW128)
#define NCH     (DD / KCH)           // 8
#define TILE_B  16384                // 128 rows x 128 B
#define STAGE_B (4 * TILE_B)         // AiH, AiL, AjH, AjL = 64 KB
#define OFF_D   131072               // stage2 aliases first 64 KB of D region
#define DSTRIDE 130
#define OFF_SQS (OFF_D + KM * DSTRIDE * 4)      // 197632
#define SMEM_TOTAL (OFF_SQS + 512)              // 198144

__device__ float          g_sqn[TN];
__device__ int            g_nn[TN * KNN];
__device__ int            g_choice_is32;
__device__ __nv_bfloat16  g_Ahi[TN * DD];
__device__ __nv_bfloat16  g_Alo[TN * DD];
__device__ int            g_cand_i[TN * 2 * NCAND];

// ============================ helpers =======================================
__device__ __forceinline__ uint32_t smem_u32(const void* p) {
    uint32_t a;
    asm("{ .reg .u64 t; cvta.to.shared.u64 t, %1; cvt.u32.u64 %0, t; }"
        : "=r"(a) : "l"(p));
    return a;
}
__device__ __forceinline__ void cp16(uint32_t dst, const void* src) {
    asm volatile("cp.async.cg.shared.global [%0], [%1], 16;"
                 :: "r"(dst), "l"(src) : "memory");
}
__device__ __forceinline__ void cp_commit() {
    asm volatile("cp.async.commit_group;" ::: "memory");
}
__device__ __forceinline__ void cp_wait0() {
    asm volatile("cp.async.wait_group 0;" ::: "memory");
}
__device__ __forceinline__ void cp_wait1() {
    asm volatile("cp.async.wait_group 1;" ::: "memory");
}
__device__ __forceinline__ void ldsm4(uint32_t* r, uint32_t a) {
    asm volatile("ldmatrix.sync.aligned.m8n8.x4.shared.b16 {%0,%1,%2,%3}, [%4];"
                 : "=r"(r[0]), "=r"(r[1]), "=r"(r[2]), "=r"(r[3]) : "r"(a));
}
__device__ __forceinline__ void mma16816(float* c, const uint32_t* a,
                                         uint32_t b0, uint32_t b1) {
    asm volatile("mma.sync.aligned.m16n8k16.row.col.f32.bf16.bf16.f32 "
                 "{%0,%1,%2,%3}, {%4,%5,%6,%7}, {%8,%9}, {%0,%1,%2,%3};"
                 : "+f"(c[0]), "+f"(c[1]), "+f"(c[2]), "+f"(c[3])
                 : "r"(a[0]), "r"(a[1]), "r"(a[2]), "r"(a[3]),
                   "r"(b0), "r"(b1));
}
__device__ __forceinline__ bool kless(float v, int id, float w, int jd) {
    return (v < w) || (v == w && id < jd);
}
template <int NC>
__device__ __forceinline__ void topk_insert(float (&kv)[NC], int (&ki)[NC],
                                            float v, int j) {
    if (kless(v, j, kv[NC - 1], ki[NC - 1])) {
        kv[NC - 1] = v; ki[NC - 1] = j;
#pragma unroll
        for (int p = NC - 1; p > 0; --p) {
            if (kless(kv[p], ki[p], kv[p - 1], ki[p - 1])) {
                float tv = kv[p]; kv[p] = kv[p - 1]; kv[p - 1] = tv;
                int   tj = ki[p]; ki[p] = ki[p - 1]; ki[p - 1] = tj;
            }
        }
    }
}

// ======================= fp32 -> bf16 hi/lo =================================
__global__ void convert_kernel(const float* __restrict__ A) {
    int idx = blockIdx.x * blockDim.x + threadIdx.x;
    float4 v = reinterpret_cast<const float4*>(A)[idx];
    __nv_bfloat16 h0 = __float2bfloat16(v.x), h1 = __float2bfloat16(v.y);
    __nv_bfloat16 h2 = __float2bfloat16(v.z), h3 = __float2bfloat16(v.w);
    __nv_bfloat16 l0 = __float2bfloat16(v.x - __bfloat162float(h0));
    __nv_bfloat16 l1 = __float2bfloat16(v.y - __bfloat162float(h1));
    __nv_bfloat16 l2 = __float2bfloat16(v.z - __bfloat162float(h2));
    __nv_bfloat16 l3 = __float2bfloat16(v.w - __bfloat162float(h3));
    __nv_bfloat162* ph = reinterpret_cast<__nv_bfloat162*>(g_Ahi);
    __nv_bfloat162* pl = reinterpret_cast<__nv_bfloat162*>(g_Alo);
    ph[idx * 2 + 0] = __nv_bfloat162(h0, h1);
    ph[idx * 2 + 1] = __nv_bfloat162(h2, h3);
    pl[idx * 2 + 0] = __nv_bfloat162(l0, l1);
    pl[idx * 2 + 1] = __nv_bfloat162(l2, l3);
}

// ============================ sq norms ======================================
__global__ void sqnorm_kernel(const float* __restrict__ A) {
    if (blockIdx.x == 0 && threadIdx.x == 0) g_choice_is32 = 0;
    int row = blockIdx.x;
    const float4* p = reinterpret_cast<const float4*>(A + (size_t)row * DD);
    float4 v = p[threadIdx.x];
    float s = v.x * v.x + v.y * v.y + v.z * v.z + v.w * v.w;
#pragma unroll
    for (int off = 16; off > 0; off >>= 1) s += __shfl_xor_sync(0xffffffffu, s, off);
    __shared__ float ws[4];
    int lane = threadIdx.x & 31, wid = threadIdx.x >> 5;
    if (lane == 0) ws[wid] = s;
    __syncthreads();
    if (threadIdx.x == 0) g_sqn[row] = ws[0] + ws[1] + ws[2] + ws[3];
}

// ===================== int32-vs-int64 detection =============================
__global__ void detect_kernel(const unsigned int* __restrict__ w) {
    int idx = blockIdx.x * blockDim.x + threadIdx.x;
    if (w[2 * idx + 1] != 0u) atomicOr(&g_choice_is32, 1);
}

// ================== tensor-core (mma.sync) kNN ==============================
// grid = 128 (64 row-blocks x 2 j-halves), 512 threads (16 warps, 4x4 grid)
__global__ __launch_bounds__(512, 1) void knn_mma_kernel() {
    extern __shared__ __align__(16) char smc[];
    const uint32_t sb = smem_u32(smc);
    const int tid  = threadIdx.x;
    const int lane = tid & 31;
    const int wid  = tid >> 5;
    const int wm   = wid >> 2;      // 0..3 -> rows wm*32
    const int wn   = wid & 3;       // 0..3 -> cols wn*32
    const int ib   = blockIdx.x >> 1;
    const int half = blockIdx.x & 1;
    const int brow = ib * KM;
    const int jbase = half * JHALF;

    float kv[NCAND]; int ki[NCAND];
#pragma unroll
    for (int s = 0; s < NCAND; ++s) { kv[s] = 3.4e38f; ki[s] = 0x7fffffff; }

    const int lrow = lane & 15;     // ldsm row within 16
    const int lcol = lane >> 4;     // 0/1 -> 16B half of k16
    const int fr = tid >> 2;        // loader: row 0..127
    const int fq0 = (tid & 3) * 2;  // loader: chunks q, q+1

    // stage smem base offsets (stage 2 aliases D region)
    auto stage_off = [](int s) -> uint32_t {
        return (s == 2) ? (uint32_t)OFF_D : (uint32_t)(s * STAGE_B);
    };

    for (int t = 0; t < NTILES; ++t) {
        const int jb = jbase + t * KNT;

        float acc[2][4][4];
#pragma unroll
        for (int a = 0; a < 2; ++a)
#pragma unroll
            for (int b = 0; b < 4; ++b)
#pragma unroll
                for (int c = 0; c < 4; ++c) acc[a][b][c] = 0.0f;

        // prologue: chunks 0 and 1 -> stages 0, 1
#pragma unroll
        for (int pc = 0; pc < 2; ++pc) {
            const uint32_t stg = sb + stage_off(pc);
            const int kt = pc * KCH;
#pragma unroll
            for (int i = 0; i < 2; ++i) {
                const int q = fq0 + i;
                const uint32_t dofs = (uint32_t)(fr * 128 + ((q ^ (fr & 7)) * 16));
                const size_t gi = (size_t)(brow + fr) * DD + kt + q * 8;
                const size_t gj = (size_t)(jb   + fr) * DD + kt + q * 8;
                cp16(stg + 0 * TILE_B + dofs, g_Ahi + gi);
                cp16(stg + 1 * TILE_B + dofs, g_Alo + gi);
                cp16(stg + 2 * TILE_B + dofs, g_Ahi + gj);
                cp16(stg + 3 * TILE_B + dofs, g_Alo + gj);
            }
            cp_commit();
        }

        for (int c = 0; c < NCH; ++c) {
            if (c == NCH - 1) cp_wait0(); else cp_wait1();
            __syncthreads();

            // prefetch chunk c+2 into stage (c+2)%3
            if (c + 2 < NCH) {
                const uint32_t stg = sb + stage_off((c + 2) % 3);
                const int kt = (c + 2) * KCH;
#pragma unroll
                for (int i = 0; i < 2; ++i) {
                    const int q = fq0 + i;
                    const uint32_t dofs = (uint32_t)(fr * 128 + ((q ^ (fr & 7)) * 16));
                    const size_t gi = (size_t)(brow + fr) * DD + kt + q * 8;
                    const size_t gj = (size_t)(jb   + fr) * DD + kt + q * 8;
                    cp16(stg + 0 * TILE_B + dofs, g_Ahi + gi);
                    cp16(stg + 1 * TILE_B + dofs, g_Alo + gi);
                    cp16(stg + 2 * TILE_B + dofs, g_Ahi + gj);
                    cp16(stg + 3 * TILE_B + dofs, g_Alo + gj);
                }
                cp_commit();
            }

            // ---- MMA on stage c%3 ----
            const uint32_t base = sb + stage_off(c % 3);
#pragma unroll
            for (int ks = 0; ks < 4; ++ks) {
                uint32_t aH[2][4], aL[2][4], bH[2][4], bL[2][4];
                const int q = ks * 2 + lcol;
                const uint32_t kof = (uint32_t)((q ^ (lrow & 7)) * 16);
#pragma unroll
                for (int mt = 0; mt < 2; ++mt) {
                    const uint32_t ad = base +
                        (uint32_t)((wm * 32 + mt * 16 + lrow) * 128) + kof;
                    ldsm4(aH[mt], ad);
                    ldsm4(aL[mt], ad + TILE_B);
                }
#pragma unroll
                for (int np = 0; np < 2; ++np) {
                    const uint32_t ad = base + 2 * TILE_B +
                        (uint32_t)((wn * 32 + np * 16 + lrow) * 128) + kof;
                    ldsm4(bH[np], ad);
                    ldsm4(bL[np], ad + TILE_B);
                }
#pragma unroll
                for (int mt = 0; mt < 2; ++mt)
#pragma unroll
                    for (int nt = 0; nt < 4; ++nt) {
                        const int np = nt >> 1, sel = nt & 1;
                        mma16816(acc[mt][nt], aH[mt], bH[np][sel], bH[np][sel + 2]);
                        mma16816(acc[mt][nt], aH[mt], bL[np][sel], bL[np][sel + 2]);
                        mma16816(acc[mt][nt], aL[mt], bH[np][sel], bH[np][sel + 2]);
                    }
            }
        }

        // ---- stage d2 dot values + sq[j] to smem ----
        if (tid < 128)
            *(float*)(smc + OFF_SQS + tid * 4) = g_sqn[jb + tid];
        {
            float* Dst = (float*)(smc + OFF_D);
            const int m0 = wm * 32 + (lane >> 2);
            const int n0 = wn * 32 + (lane & 3) * 2;
#pragma unroll
            for (int mt = 0; mt < 2; ++mt)
#pragma unroll
                for (int nt = 0; nt < 4; ++nt) {
                    *(float2*)(Dst + (m0 + mt * 16    ) * DSTRIDE + n0 + nt * 8) =
                        make_float2(acc[mt][nt][0], acc[mt][nt][1]);
                    *(float2*)(Dst + (m0 + mt * 16 + 8) * DSTRIDE + n0 + nt * 8) =
                        make_float2(acc[mt][nt][2], acc[mt][nt][3]);
                }
        }
        __syncthreads();

        // ---- selection: 4 threads per row, 32 cols each ----
        {
            const int row = tid & 127, qtr = tid >> 7;
            const int grow = brow + row;
            const float* Dp  = (const float*)(smc + OFF_D) + row * DSTRIDE + qtr * 32;
            const float* sqp = (const float*)(smc + OFF_SQS) + qtr * 32;
            const int j0 = jb + qtr * 32;
#pragma unroll 8
            for (int n = 0; n < 32; ++n) {
                int j = j0 + n;
                float val = sqp[n] - 2.0f * Dp[n];
                if (j != grow) topk_insert<NCAND>(kv, ki, val, j);
            }
        }
        // selection reads of D (stage-2 alias) are fenced from next tile's
        // stage-2 prefetch by the c=0 __syncthreads of the next chunk loop
    }

    // ---- merge the 4 per-row thread lists, write candidates ---------------
    __syncthreads();
    {
        float* mv = (float*)(smc + OFF_D);
        int*   mi = (int*)(smc + OFF_D) + 512 * NCAND;
#pragma unroll
        for (int s = 0; s < NCAND; ++s) {
            mv[tid * NCAND + s] = kv[s];
            mi[tid * NCAND + s] = ki[s];
        }
    }
    __syncthreads();
    if (tid < 128) {
        float* mv = (float*)(smc + OFF_D);
        int*   mi = (int*)(smc + OFF_D) + 512 * NCAND;
#pragma unroll
        for (int o = 1; o < 4; ++o) {
            const int b = (tid + o * 128) * NCAND;
#pragma unroll
            for (int s = 0; s < NCAND; ++s)
                topk_insert<NCAND>(kv, ki, mv[b + s], mi[b + s]);
        }
        const int grow = brow + tid;
        const int base = (grow * 2 + half) * NCAND;
#pragma unroll
        for (int s = 0; s < NCAND; ++s) g_cand_i[base + s] = ki[s];
    }
}

// ========= exact fp32 rescore of 16 candidates -> top-5 =====================
__global__ void rescore_kernel(const float* __restrict__ A) {
    const int row = blockIdx.x;
    const int w = threadIdx.x >> 5, lane = threadIdx.x & 31;  // 16 warps
    __shared__ float sv[16];
    __shared__ int   si[16];
    const int j = g_cand_i[row * 16 + w];
    const float* ai = A + (size_t)row * DD;
    const float* aj = A + (size_t)j * DD;
    float dot = 0.0f;
#pragma unroll
    for (int k = 0; k < 16; ++k) dot += ai[lane + k * 32] * aj[lane + k * 32];
#pragma unroll
    for (int off = 16; off > 0; off >>= 1) dot += __shfl_xor_sync(0xffffffffu, dot, off);
    if (lane == 0) { sv[w] = g_sqn[j] - 2.0f * dot; si[w] = j; }
    __syncthreads();
    if (threadIdx.x == 0) {
        float bv[KNN]; int bi[KNN];
#pragma unroll
        for (int s = 0; s < KNN; ++s) { bv[s] = 3.4e38f; bi[s] = 0x7fffffff; }
        for (int e = 0; e < 16; ++e) {
            float v = sv[e]; int id = si[e];
            if (kless(v, id, bv[KNN - 1], bi[KNN - 1])) {
                bv[KNN - 1] = v; bi[KNN - 1] = id;
#pragma unroll
                for (int p = KNN - 1; p > 0; --p) {
                    if (kless(bv[p], bi[p], bv[p - 1], bi[p - 1])) {
                        float fv = bv[p]; bv[p] = bv[p - 1]; bv[p - 1] = fv;
                        int   iv = bi[p]; bi[p] = bi[p - 1]; bi[p - 1] = iv;
                    }
                }
            }
        }
#pragma unroll
        for (int s = 0; s < KNN; ++s) g_nn[row * KNN + s] = bi[s];
    }
}

// ===================== SMOTE interpolation ==================================
__global__ void populate_kernel(const float* __restrict__ A,
                                const float* __restrict__ gaps,
                                const unsigned int* __restrict__ cw,
                                float* __restrict__ out) {
    int o = blockIdx.x;
    int i = o >> 2;
    float g = gaps[o];
    int widx = g_choice_is32 ? o : (o << 1);
    int c  = (int)cw[widx];
    int nb = g_nn[i * KNN + c];
    const float4* ai = reinterpret_cast<const float4*>(A + (size_t)i  * DD);
    const float4* an = reinterpret_cast<const float4*>(A + (size_t)nb * DD);
    float4* op = reinterpret_cast<float4*>(out) + (size_t)o * (DD / 4);
    int t = threadIdx.x;
    float4 a = ai[t], b = an[t];
    float4 r;
    r.x = a.x + g * (b.x - a.x);
    r.y = a.y + g * (b.y - a.y);
    r.z = a.z + g * (b.z - a.z);
    r.w = a.w + g * (b.w - a.w);
    op[t] = r;
}

// ============================================================================
extern "C" void kernel_launch(void* const* d_in, const int* in_sizes, int n_in,
                              void* d_out, int out_size) {
    const float* A         = (const float*)d_in[0];
    const float* gaps      = (const float*)d_in[1];
    const unsigned int* cw = (const unsigned int*)d_in[2];
    float* out             = (float*)d_out;

    cudaFuncSetAttribute(knn_mma_kernel,
                         cudaFuncAttributeMaxDynamicSharedMemorySize, SMEM_TOTAL);

    convert_kernel<<<TN * DD / 4 / 256, 256>>>(A);
    sqnorm_kernel<<<TN, 128>>>(A);
    detect_kernel<<<64, 256>>>(cw);
    knn_mma_kernel<<<128, 512, SMEM_TOTAL>>>();
    rescore_kernel<<<TN, 512>>>(A);
    populate_kernel<<<TN * NPER, 128>>>(A, gaps, cw, out);
}

// round 5
// speedup vs baseline: 2.8635x; 1.0265x over previous
#include <cuda_runtime.h>
#include <cuda_bf16.h>
#include <cstdint>

#define TN    8192
#define DD    512
#define NPER  4
#define KNN   5
#define NCAND 8

#define KM      128
#define KNT     128
#define JHALF   (TN / 2)
#define NTILES  (JHALF / KNT)        // 32
#define KCH     64                   // bf16 k per chunk (128B rows, SW128)
#define NCH     (DD / KCH)           // 8
#define TILE_B  16384                // 128 rows x 128 B
#define STAGE_B (4 * TILE_B)         // AiH, AiL, AjH, AjL = 64 KB
#define OFF_D   131072               // stage2 aliases first 64 KB of D region
#define DSTRIDE 130
#define OFF_SQS (OFF_D + KM * DSTRIDE * 4)      // 197632
#define SMEM_TOTAL (OFF_SQS + 512)              // 198144

__device__ float          g_sqn[TN];
__device__ int            g_nn[TN * KNN];
__device__ int            g_choice_is32;
__device__ __nv_bfloat16  g_Ahi[TN * DD];
__device__ __nv_bfloat16  g_Alo[TN * DD];
__device__ int            g_cand_i[TN * 2 * NCAND];

// ============================ helpers =======================================
__device__ __forceinline__ uint32_t smem_u32(const void* p) {
    uint32_t a;
    asm("{ .reg .u64 t; cvta.to.shared.u64 t, %1; cvt.u32.u64 %0, t; }"
        : "=r"(a) : "l"(p));
    return a;
}
__device__ __forceinline__ void cp16(uint32_t dst, const void* src) {
    asm volatile("cp.async.cg.shared.global [%0], [%1], 16;"
                 :: "r"(dst), "l"(src) : "memory");
}
__device__ __forceinline__ void cp_commit() {
    asm volatile("cp.async.commit_group;" ::: "memory");
}
__device__ __forceinline__ void cp_wait0() {
    asm volatile("cp.async.wait_group 0;" ::: "memory");
}
__device__ __forceinline__ void cp_wait1() {
    asm volatile("cp.async.wait_group 1;" ::: "memory");
}
__device__ __forceinline__ void ldsm4(uint32_t* r, uint32_t a) {
    asm volatile("ldmatrix.sync.aligned.m8n8.x4.shared.b16 {%0,%1,%2,%3}, [%4];"
                 : "=r"(r[0]), "=r"(r[1]), "=r"(r[2]), "=r"(r[3]) : "r"(a));
}
__device__ __forceinline__ void mma16816(float* c, const uint32_t* a,
                                         uint32_t b0, uint32_t b1) {
    asm volatile("mma.sync.aligned.m16n8k16.row.col.f32.bf16.bf16.f32 "
                 "{%0,%1,%2,%3}, {%4,%5,%6,%7}, {%8,%9}, {%0,%1,%2,%3};"
                 : "+f"(c[0]), "+f"(c[1]), "+f"(c[2]), "+f"(c[3])
                 : "r"(a[0]), "r"(a[1]), "r"(a[2]), "r"(a[3]),
                   "r"(b0), "r"(b1));
}
__device__ __forceinline__ bool kless(float v, int id, float w, int jd) {
    return (v < w) || (v == w && id < jd);
}
template <int NC>
__device__ __forceinline__ void topk_insert(float (&kv)[NC], int (&ki)[NC],
                                            float v, int j) {
    if (kless(v, j, kv[NC - 1], ki[NC - 1])) {
        kv[NC - 1] = v; ki[NC - 1] = j;
#pragma unroll
        for (int p = NC - 1; p > 0; --p) {
            if (kless(kv[p], ki[p], kv[p - 1], ki[p - 1])) {
                float tv = kv[p]; kv[p] = kv[p - 1]; kv[p - 1] = tv;
                int   tj = ki[p]; ki[p] = ki[p - 1]; ki[p - 1] = tj;
            }
        }
    }
}

// ======================= fp32 -> bf16 hi/lo =================================
__global__ void convert_kernel(const float* __restrict__ A) {
    int idx = blockIdx.x * blockDim.x + threadIdx.x;
    float4 v = reinterpret_cast<const float4*>(A)[idx];
    __nv_bfloat16 h0 = __float2bfloat16(v.x), h1 = __float2bfloat16(v.y);
    __nv_bfloat16 h2 = __float2bfloat16(v.z), h3 = __float2bfloat16(v.w);
    __nv_bfloat16 l0 = __float2bfloat16(v.x - __bfloat162float(h0));
    __nv_bfloat16 l1 = __float2bfloat16(v.y - __bfloat162float(h1));
    __nv_bfloat16 l2 = __float2bfloat16(v.z - __bfloat162float(h2));
    __nv_bfloat16 l3 = __float2bfloat16(v.w - __bfloat162float(h3));
    __nv_bfloat162* ph = reinterpret_cast<__nv_bfloat162*>(g_Ahi);
    __nv_bfloat162* pl = reinterpret_cast<__nv_bfloat162*>(g_Alo);
    ph[idx * 2 + 0] = __nv_bfloat162(h0, h1);
    ph[idx * 2 + 1] = __nv_bfloat162(h2, h3);
    pl[idx * 2 + 0] = __nv_bfloat162(l0, l1);
    pl[idx * 2 + 1] = __nv_bfloat162(l2, l3);
}

// ============================ sq norms ======================================
__global__ void sqnorm_kernel(const float* __restrict__ A) {
    if (blockIdx.x == 0 && threadIdx.x == 0) g_choice_is32 = 0;
    int row = blockIdx.x;
    const float4* p = reinterpret_cast<const float4*>(A + (size_t)row * DD);
    float4 v = p[threadIdx.x];
    float s = v.x * v.x + v.y * v.y + v.z * v.z + v.w * v.w;
#pragma unroll
    for (int off = 16; off > 0; off >>= 1) s += __shfl_xor_sync(0xffffffffu, s, off);
    __shared__ float ws[4];
    int lane = threadIdx.x & 31, wid = threadIdx.x >> 5;
    if (lane == 0) ws[wid] = s;
    __syncthreads();
    if (threadIdx.x == 0) g_sqn[row] = ws[0] + ws[1] + ws[2] + ws[3];
}

// ===================== int32-vs-int64 detection =============================
__global__ void detect_kernel(const unsigned int* __restrict__ w) {
    int idx = blockIdx.x * blockDim.x + threadIdx.x;
    if (w[2 * idx + 1] != 0u) atomicOr(&g_choice_is32, 1);
}

// ================== tensor-core (mma.sync) kNN ==============================
// grid = 128 (64 row-blocks x 2 j-halves), 1024 threads (32 warps, 4x8 grid)
// warp tile 32x16: rows wm*32 (2 x m16), cols wn*16 (2 x n8 from one ldsm4)
__global__ __launch_bounds__(1024, 1) void knn_mma_kernel() {
    extern __shared__ __align__(16) char smc[];
    const uint32_t sb = smem_u32(smc);
    const int tid  = threadIdx.x;
    const int lane = tid & 31;
    const int wid  = tid >> 5;
    const int wm   = wid >> 3;      // 0..3 -> rows wm*32
    const int wn   = wid & 7;       // 0..7 -> cols wn*16
    const int ib   = blockIdx.x >> 1;
    const int half = blockIdx.x & 1;
    const int brow = ib * KM;
    const int jbase = half * JHALF;

    float kv[NCAND]; int ki[NCAND];
#pragma unroll
    for (int s = 0; s < NCAND; ++s) { kv[s] = 3.4e38f; ki[s] = 0x7fffffff; }

    const int lrow = lane & 15;     // ldsm row within 16
    const int lcol = lane >> 4;     // 0/1 -> 16B half of k16
    const int fr = tid >> 3;        // loader: row 0..127
    const int fq = tid & 7;         // loader: 16B quad 0..7
    const uint32_t fofs = (uint32_t)(fr * 128 + ((fq ^ (fr & 7)) * 16));

    // stage smem base offsets (stage 2 aliases D region)
    auto stage_off = [](int s) -> uint32_t {
        return (s == 2) ? (uint32_t)OFF_D : (uint32_t)(s * STAGE_B);
    };

    for (int t = 0; t < NTILES; ++t) {
        const int jb = jbase + t * KNT;

        float acc[2][2][4];
#pragma unroll
        for (int a = 0; a < 2; ++a)
#pragma unroll
            for (int b = 0; b < 2; ++b)
#pragma unroll
                for (int c = 0; c < 4; ++c) acc[a][b][c] = 0.0f;

        // prologue: chunks 0 and 1 -> stages 0, 1
#pragma unroll
        for (int pc = 0; pc < 2; ++pc) {
            const uint32_t stg = sb + stage_off(pc);
            const int kt = pc * KCH;
            const size_t gi = (size_t)(brow + fr) * DD + kt + fq * 8;
            const size_t gj = (size_t)(jb   + fr) * DD + kt + fq * 8;
            cp16(stg + 0 * TILE_B + fofs, g_Ahi + gi);
            cp16(stg + 1 * TILE_B + fofs, g_Alo + gi);
            cp16(stg + 2 * TILE_B + fofs, g_Ahi + gj);
            cp16(stg + 3 * TILE_B + fofs, g_Alo + gj);
            cp_commit();
        }

        for (int c = 0; c < NCH; ++c) {
            if (c == NCH - 1) cp_wait0(); else cp_wait1();
            __syncthreads();

            // prefetch chunk c+2 into stage (c+2)%3
            if (c + 2 < NCH) {
                const uint32_t stg = sb + stage_off((c + 2) % 3);
                const int kt = (c + 2) * KCH;
                const size_t gi = (size_t)(brow + fr) * DD + kt + fq * 8;
                const size_t gj = (size_t)(jb   + fr) * DD + kt + fq * 8;
                cp16(stg + 0 * TILE_B + fofs, g_Ahi + gi);
                cp16(stg + 1 * TILE_B + fofs, g_Alo + gi);
                cp16(stg + 2 * TILE_B + fofs, g_Ahi + gj);
                cp16(stg + 3 * TILE_B + fofs, g_Alo + gj);
                cp_commit();
            }

            // ---- MMA on stage c%3 ----
            const uint32_t base = sb + stage_off(c % 3);
#pragma unroll
            for (int ks = 0; ks < 4; ++ks) {
                uint32_t aH[2][4], aL[2][4], bH[4], bL[4];
                const int q = ks * 2 + lcol;
                const uint32_t kof = (uint32_t)((q ^ (lrow & 7)) * 16);
#pragma unroll
                for (int mt = 0; mt < 2; ++mt) {
                    const uint32_t ad = base +
                        (uint32_t)((wm * 32 + mt * 16 + lrow) * 128) + kof;
                    ldsm4(aH[mt], ad);
                    ldsm4(aL[mt], ad + TILE_B);
                }
                {
                    const uint32_t ad = base + 2 * TILE_B +
                        (uint32_t)((wn * 16 + lrow) * 128) + kof;
                    ldsm4(bH, ad);
                    ldsm4(bL, ad + TILE_B);
                }
#pragma unroll
                for (int mt = 0; mt < 2; ++mt)
#pragma unroll
                    for (int sel = 0; sel < 2; ++sel) {
                        mma16816(acc[mt][sel], aH[mt], bH[sel], bH[sel + 2]);
                        mma16816(acc[mt][sel], aH[mt], bL[sel], bL[sel + 2]);
                        mma16816(acc[mt][sel], aL[mt], bH[sel], bH[sel + 2]);
                    }
            }
        }

        // ---- stage d2 dot values + sq[j] to smem ----
        if (tid < 128)
            *(float*)(smc + OFF_SQS + tid * 4) = g_sqn[jb + tid];
        {
            float* Dst = (float*)(smc + OFF_D);
            const int m0 = wm * 32 + (lane >> 2);
            const int n0 = wn * 16 + (lane & 3) * 2;
#pragma unroll
            for (int mt = 0; mt < 2; ++mt)
#pragma unroll
                for (int sel = 0; sel < 2; ++sel) {
                    *(float2*)(Dst + (m0 + mt * 16    ) * DSTRIDE + n0 + sel * 8) =
                        make_float2(acc[mt][sel][0], acc[mt][sel][1]);
                    *(float2*)(Dst + (m0 + mt * 16 + 8) * DSTRIDE + n0 + sel * 8) =
                        make_float2(acc[mt][sel][2], acc[mt][sel][3]);
                }
        }
        __syncthreads();

        // ---- selection: 8 threads per row, 16 cols each ----
        {
            const int row = tid & 127, oct = tid >> 7;
            const int grow = brow + row;
            const float* Dp  = (const float*)(smc + OFF_D) + row * DSTRIDE + oct * 16;
            const float* sqp = (const float*)(smc + OFF_SQS) + oct * 16;
            const int j0 = jb + oct * 16;
#pragma unroll
            for (int n = 0; n < 16; ++n) {
                int j = j0 + n;
                float val = sqp[n] - 2.0f * Dp[n];
                if (j != grow) topk_insert<NCAND>(kv, ki, val, j);
            }
        }
        // selection reads of D (stage-2 alias) are fenced from the next
        // tile's stage-2 prefetch by the c=0 __syncthreads of the next loop
    }

    // ---- merge the 8 per-row thread lists, write candidates ---------------
    __syncthreads();
    {
        float* mv = (float*)(smc + OFF_D);
        int*   mi = (int*)(smc + OFF_D) + 1024 * NCAND;
#pragma unroll
        for (int s = 0; s < NCAND; ++s) {
            mv[tid * NCAND + s] = kv[s];
            mi[tid * NCAND + s] = ki[s];
        }
    }
    __syncthreads();
    if (tid < 128) {
        float* mv = (float*)(smc + OFF_D);
        int*   mi = (int*)(smc + OFF_D) + 1024 * NCAND;
#pragma unroll
        for (int o = 1; o < 8; ++o) {
            const int b = (tid + o * 128) * NCAND;
#pragma unroll
            for (int s = 0; s < NCAND; ++s)
                topk_insert<NCAND>(kv, ki, mv[b + s], mi[b + s]);
        }
        const int grow = brow + tid;
        const int base = (grow * 2 + half) * NCAND;
#pragma unroll
        for (int s = 0; s < NCAND; ++s) g_cand_i[base + s] = ki[s];
    }
}

// ========= exact fp32 rescore of 16 candidates -> top-5 =====================
__global__ void rescore_kernel(const float* __restrict__ A) {
    const int row = blockIdx.x;
    const int w = threadIdx.x >> 5, lane = threadIdx.x & 31;  // 16 warps
    __shared__ float sv[16];
    __shared__ int   si[16];
    const int j = g_cand_i[row * 16 + w];
    const float* ai = A + (size_t)row * DD;
    const float* aj = A + (size_t)j * DD;
    float dot = 0.0f;
#pragma unroll
    for (int k = 0; k < 16; ++k) dot += ai[lane + k * 32] * aj[lane + k * 32];
#pragma unroll
    for (int off = 16; off > 0; off >>= 1) dot += __shfl_xor_sync(0xffffffffu, dot, off);
    if (lane == 0) { sv[w] = g_sqn[j] - 2.0f * dot; si[w] = j; }
    __syncthreads();
    if (threadIdx.x == 0) {
        float bv[KNN]; int bi[KNN];
#pragma unroll
        for (int s = 0; s < KNN; ++s) { bv[s] = 3.4e38f; bi[s] = 0x7fffffff; }
        for (int e = 0; e < 16; ++e) {
            float v = sv[e]; int id = si[e];
            if (kless(v, id, bv[KNN - 1], bi[KNN - 1])) {
                bv[KNN - 1] = v; bi[KNN - 1] = id;
#pragma unroll
                for (int p = KNN - 1; p > 0; --p) {
                    if (kless(bv[p], bi[p], bv[p - 1], bi[p - 1])) {
                        float fv = bv[p]; bv[p] = bv[p - 1]; bv[p - 1] = fv;
                        int   iv = bi[p]; bi[p] = bi[p - 1]; bi[p - 1] = iv;
                    }
                }
            }
        }
#pragma unroll
        for (int s = 0; s < KNN; ++s) g_nn[row * KNN + s] = bi[s];
    }
}

// ===================== SMOTE interpolation ==================================
__global__ void populate_kernel(const float* __restrict__ A,
                                const float* __restrict__ gaps,
                                const unsigned int* __restrict__ cw,
                                float* __restrict__ out) {
    int o = blockIdx.x;
    int i = o >> 2;
    float g = gaps[o];
    int widx = g_choice_is32 ? o : (o << 1);
    int c  = (int)cw[widx];
    int nb = g_nn[i * KNN + c];
    const float4* ai = reinterpret_cast<const float4*>(A + (size_t)i  * DD);
    const float4* an = reinterpret_cast<const float4*>(A + (size_t)nb * DD);
    float4* op = reinterpret_cast<float4*>(out) + (size_t)o * (DD / 4);
    int t = threadIdx.x;
    float4 a = ai[t], b = an[t];
    float4 r;
    r.x = a.x + g * (b.x - a.x);
    r.y = a.y + g * (b.y - a.y);
    r.z = a.z + g * (b.z - a.z);
    r.w = a.w + g * (b.w - a.w);
    op[t] = r;
}

// ============================================================================
extern "C" void kernel_launch(void* const* d_in, const int* in_sizes, int n_in,
                              void* d_out, int out_size) {
    const float* A         = (const float*)d_in[0];
    const float* gaps      = (const float*)d_in[1];
    const unsigned int* cw = (const unsigned int*)d_in[2];
    float* out             = (float*)d_out;

    cudaFuncSetAttribute(knn_mma_kernel,
                         cudaFuncAttributeMaxDynamicSharedMemorySize, SMEM_TOTAL);

    convert_kernel<<<TN * DD / 4 / 256, 256>>>(A);
    sqnorm_kernel<<<TN, 128>>>(A);
    detect_kernel<<<64, 256>>>(cw);
    knn_mma_kernel<<<128, 1024, SMEM_TOTAL>>>();
    rescore_kernel<<<TN, 512>>>(A);
    populate_kernel<<<TN * NPER, 128>>>(A, gaps, cw, out);
}